// round 13
// baseline (speedup 1.0000x reference)
#include <cuda_runtime.h>
#include <cuda_bf16.h>
#include <cuda_fp16.h>
#include <cstdint>

#define NN 100000
#define NE 1600000
#define F0 256
#define F1 128
#define F2 64
#define NBLK_SCAN 98   // ceil(NN/1024)
#define NTILE 782      // ceil(NN/128)

// ---- scratch (device globals; no allocation allowed) ----
__device__ __align__(16) __half g_h1[NN * F1];   // x @ W1            (fp16 gather operand)
__device__ __align__(16) __half g_h2[NN * F2];   // dinv*(hr @ W2)    (fp16, pre-scaled)
__device__ float g_dinv[NN];
__device__ int   g_deg[NN];
__device__ int   g_rowstart[NN];
__device__ int   g_cursor[NN];
__device__ int   g_csr[NE];
__device__ int   g_dst[NE];
__device__ int   g_is32;
__device__ int   g_part[128];
__device__ int   g_base[128];
// W1, W2 split into fp16 hi/lo (row-major [k][n])
__device__ __align__(16) __half g_w1h[F0 * F1];
__device__ __align__(16) __half g_w1l[F0 * F1];
__device__ __align__(16) __half g_w2h[F1 * F2];
__device__ __align__(16) __half g_w2l[F1 * F2];

// ================= mma.sync helpers (sm_80+ PTX; safe on base sm_103) =========
__device__ __forceinline__ uint32_t s2u(const void* p) {
    uint32_t a;
    asm("{ .reg .u64 t; cvta.to.shared.u64 t, %1; cvt.u32.u64 %0, t; }" : "=r"(a) : "l"(p));
    return a;
}

__device__ __forceinline__ void ldsm4(uint32_t* r, uint32_t a) {
    asm volatile("ldmatrix.sync.aligned.m8n8.x4.shared.b16 {%0,%1,%2,%3}, [%4];"
                 : "=r"(r[0]), "=r"(r[1]), "=r"(r[2]), "=r"(r[3]) : "r"(a));
}
__device__ __forceinline__ void ldsm4t(uint32_t* r, uint32_t a) {
    asm volatile("ldmatrix.sync.aligned.m8n8.x4.trans.shared.b16 {%0,%1,%2,%3}, [%4];"
                 : "=r"(r[0]), "=r"(r[1]), "=r"(r[2]), "=r"(r[3]) : "r"(a));
}
__device__ __forceinline__ void mma16816h(float* c, const uint32_t* a,
                                          uint32_t b0, uint32_t b1) {
    asm volatile("mma.sync.aligned.m16n8k16.row.col.f32.f16.f16.f32 "
                 "{%0,%1,%2,%3}, {%4,%5,%6,%7}, {%8,%9}, {%0,%1,%2,%3};"
                 : "+f"(c[0]), "+f"(c[1]), "+f"(c[2]), "+f"(c[3])
                 : "r"(a[0]), "r"(a[1]), "r"(a[2]), "r"(a[3]), "r"(b0), "r"(b1));
}

// -------- combined degree init + edge dtype detect --------
__global__ void k_deg_init_detect(const void* __restrict__ ei) {
    int i = blockIdx.x * blockDim.x + threadIdx.x;
    if (i < NN) g_deg[i] = 1;   // +1 self loop baked in
    if (i == 0) {
        const long long* e64 = (const long long*)ei;
        int ok64 = 1;
        for (int j = 0; j < 128; j++) {
            long long v = e64[j];
            if (v < 0 || v >= NN) { ok64 = 0; break; }
        }
        g_is32 = ok64 ? 0 : 1;
    }
}

__global__ void k_convert(const void* __restrict__ ei) {
    int i = blockIdx.x * blockDim.x + threadIdx.x;
    if (i >= NE) return;
    int v;
    if (g_is32) v = ((const int*)ei)[NE + i];
    else        v = (int)((const long long*)ei)[NE + i];
    g_dst[i] = v;
    if (v >= 0 && v < NN) atomicAdd(&g_deg[v], 1);   // fused degree count
}

__global__ void k_dinv() {
    int i = blockIdx.x * blockDim.x + threadIdx.x;
    if (i < NN) g_dinv[i] = rsqrtf((float)g_deg[i]);
}

// ---------------- W split to fp16 hi/lo ----------------
__global__ void k_wsplit(const float* __restrict__ W1, const float* __restrict__ W2) {
    int i = blockIdx.x * blockDim.x + threadIdx.x;
    if (i < F0 * F1) {
        float v = W1[i];
        __half h = __float2half_rn(v);
        g_w1h[i] = h;
        g_w1l[i] = __float2half_rn(v - __half2float(h));
    } else if (i < F0 * F1 + F1 * F2) {
        int j = i - F0 * F1;
        float v = W2[j];
        __half h = __float2half_rn(v);
        g_w2h[j] = h;
        g_w2l[j] = __float2half_rn(v - __half2float(h));
    }
}

// ---------------- CSR build: shfl-based scans, then cursor fill ----------------
__global__ void k_scan_partial() {
    int t = threadIdx.x;
    int i = blockIdx.x * 1024 + t;
    int v = (i < NN) ? (g_deg[i] - 1) : 0;
    #pragma unroll
    for (int o = 16; o > 0; o >>= 1) v += __shfl_xor_sync(0xFFFFFFFFu, v, o);
    __shared__ int ws[32];
    if ((t & 31) == 0) ws[t >> 5] = v;
    __syncthreads();
    if (t < 32) {
        int s = ws[t];
        #pragma unroll
        for (int o = 16; o > 0; o >>= 1) s += __shfl_xor_sync(0xFFFFFFFFu, s, o);
        if (t == 0) g_part[blockIdx.x] = s;
    }
}

__global__ void k_scan_base() {
    __shared__ int s[128];
    int t = threadIdx.x;
    int v = (t < NBLK_SCAN) ? g_part[t] : 0;
    s[t] = v;
    __syncthreads();
    for (int off = 1; off < 128; off <<= 1) {
        int u = (t >= off) ? s[t - off] : 0;
        __syncthreads();
        s[t] += u;
        __syncthreads();
    }
    if (t < NBLK_SCAN) g_base[t] = s[t] - v;  // exclusive
}

__global__ void k_scan_write() {
    int t = threadIdx.x, lane = t & 31, w = t >> 5;
    int i = blockIdx.x * 1024 + t;
    int v = (i < NN) ? (g_deg[i] - 1) : 0;
    int x = v;
    #pragma unroll
    for (int o = 1; o < 32; o <<= 1) {
        int u = __shfl_up_sync(0xFFFFFFFFu, x, o);
        if (lane >= o) x += u;
    }
    __shared__ int ws[32];
    if (lane == 31) ws[w] = x;
    __syncthreads();
    if (t < 32) {
        int s = ws[t];
        #pragma unroll
        for (int o = 1; o < 32; o <<= 1) {
            int u = __shfl_up_sync(0xFFFFFFFFu, s, o);
            if (lane >= o) s += u;
        }
        ws[t] = s;
    }
    __syncthreads();
    if (i < NN) {
        int base = g_base[blockIdx.x] + (w > 0 ? ws[w - 1] : 0);
        int start = base + x - v;   // exclusive prefix
        g_rowstart[i] = start;
        g_cursor[i]   = start;
    }
}

__global__ void k_fill(const void* __restrict__ ei) {
    int i = blockIdx.x * blockDim.x + threadIdx.x;
    if (i < NE) {
        int d = g_dst[i];
        if (d < 0 || d >= NN) return;
        int s;
        if (g_is32) s = ((const int*)ei)[i];
        else        s = (int)((const long long*)ei)[i];
        int pos = atomicAdd(&g_cursor[d], 1);
        if (pos >= 0 && pos < NE) g_csr[pos] = s;
    }
}

// =======================================================================
// GEMM1 (fp16 A exact, W1 split fp16 hi/lo, 2-pass):
//   g_h1[M,128](fp16) = x[M,256](fp32->fp16) @ W1
// =======================================================================
__global__ void __launch_bounds__(256, 2) k_mma1(const float* __restrict__ Ain) {
    constexpr int NC = F1, KT = F0;
    constexpr int KC   = 32;
    constexpr int AST  = 40;
    constexpr int BST  = NC + 8;
    constexpr int NWN  = NC / 2;
    constexpr int NT8  = NWN / 8;
    constexpr int NT16 = NWN / 16;
    constexpr int NC4  = NC / 4;

    __shared__ __align__(16) __half Ax[128 * AST];
    __shared__ __align__(16) __half Bh[KC * BST];
    __shared__ __align__(16) __half Bl[KC * BST];

    const int tid = threadIdx.x, lane = tid & 31, wid = tid >> 5;
    const int warp_m = wid & 3, warp_n = wid >> 2;
    const int rbase = blockIdx.x * 128;

    const uint32_t ax_b = s2u(Ax);
    const uint32_t bh_b = s2u(Bh), bl_b = s2u(Bl);

    float acc[2][NT8][4];
    #pragma unroll
    for (int a = 0; a < 2; a++)
        #pragma unroll
        for (int b = 0; b < NT8; b++)
            #pragma unroll
            for (int c = 0; c < 4; c++) acc[a][b][c] = 0.f;

    const int a_row = (lane & 15);
    const int a_col = 8 * (lane >> 4);
    const int b_row = (lane & 15);
    const int b_col = 8 * (lane >> 4);

    const float4* av = (const float4*)Ain;
    constexpr int ROWF4 = KT / 4;

    for (int ch = 0; ch < KT / KC; ch++) {
        const int c0 = ch * KC;

        #pragma unroll
        for (int i = 0; i < 4; i++) {
            int idx = tid + i * 256;
            int r = idx >> 3;
            int f = idx & 7;
            float4 v = make_float4(0.f, 0.f, 0.f, 0.f);
            int gr = rbase + r;
            if (gr < NN) v = av[(size_t)gr * ROWF4 + (c0 >> 2) + f];
            uint2 p;
            *(__half2*)&p.x = __floats2half2_rn(v.x, v.y);
            *(__half2*)&p.y = __floats2half2_rn(v.z, v.w);
            *(uint2*)&Ax[r * AST + f * 4] = p;
        }

        #pragma unroll
        for (int i = 0; i < (KC * NC4) / 256; i++) {
            int idx = tid + i * 256;
            int k = idx / NC4, n4 = idx % NC4;
            int e = k * BST + n4 * 4;
            size_t ge = (size_t)(c0 + k) * NC + n4 * 4;
            *(uint2*)&Bh[e] = *(const uint2*)&g_w1h[ge];
            *(uint2*)&Bl[e] = *(const uint2*)&g_w1l[ge];
        }
        __syncthreads();

        #pragma unroll
        for (int ks = 0; ks < 2; ks++) {
            const int k16 = ks * 16;
            uint32_t af[2][4];
            #pragma unroll
            for (int mi = 0; mi < 2; mi++) {
                uint32_t off = (uint32_t)(((warp_m * 32 + mi * 16 + a_row) * AST
                                           + k16 + a_col) * 2);
                ldsm4(af[mi], ax_b + off);
            }
            #pragma unroll
            for (int ni = 0; ni < NT16; ni++) {
                uint32_t off = (uint32_t)(((k16 + b_row) * BST
                                           + warp_n * NWN + ni * 16 + b_col) * 2);
                uint32_t bfh[4], bfl[4];
                ldsm4t(bfh, bh_b + off);
                ldsm4t(bfl, bl_b + off);
                #pragma unroll
                for (int mi = 0; mi < 2; mi++) {
                    mma16816h(acc[mi][2 * ni],     af[mi], bfh[0], bfh[1]);
                    mma16816h(acc[mi][2 * ni + 1], af[mi], bfh[2], bfh[3]);
                    mma16816h(acc[mi][2 * ni],     af[mi], bfl[0], bfl[1]);
                    mma16816h(acc[mi][2 * ni + 1], af[mi], bfl[2], bfl[3]);
                }
            }
        }
        __syncthreads();
    }

    const int g = lane >> 2, tig = lane & 3;
    #pragma unroll
    for (int mi = 0; mi < 2; mi++) {
        int row0 = rbase + warp_m * 32 + mi * 16 + g;
        #pragma unroll
        for (int ni = 0; ni < NT8; ni++) {
            int col = warp_n * NWN + ni * 8 + tig * 2;
            if (row0 < NN)
                *(__half2*)&g_h1[(size_t)row0 * NC + col] =
                    __floats2half2_rn(acc[mi][ni][0], acc[mi][ni][1]);
            if (row0 + 8 < NN)
                *(__half2*)&g_h1[(size_t)(row0 + 8) * NC + col] =
                    __floats2half2_rn(acc[mi][ni][2], acc[mi][ni][3]);
        }
    }
}

// =======================================================================
// FUSED agg1 + GEMM2:
//   Phase 1: per-CTA, aggregate 128 rows (warp-per-row, lane = 4 channels):
//            hr[row] = relu(sum_src dd*dinv[src]*h1[src] + dd^2*h1[row] + b1)
//            -> written as fp16 straight into the GEMM A smem tile.
//   Phase 2: g_h2[row] = dinv[row] * (hr_tile @ W2)   (fp16 A exact, 2-pass)
// The g_hr global round-trip is eliminated entirely.
// =======================================================================
__global__ void __launch_bounds__(256, 2) k_agg1_mma2(const float* __restrict__ b1) {
    constexpr int NC = F2, KT = F1;
    constexpr int KC   = 32;
    constexpr int AST  = KT + 8;     // 136 halves/row (272B) -> ldmatrix conflict-free
    constexpr int BST  = NC + 8;     // 72
    constexpr int NWN  = NC / 2;     // 32
    constexpr int NT8  = NWN / 8;    // 4
    constexpr int NT16 = NWN / 16;   // 2
    constexpr int NC4  = NC / 4;     // 16

    __shared__ __align__(16) __half Ax[128 * AST];   // 34816 B
    __shared__ __align__(16) __half Bh[KC * BST];    //  4608 B
    __shared__ __align__(16) __half Bl[KC * BST];    //  4608 B

    const int tid = threadIdx.x, lane = tid & 31, wid = tid >> 5;
    const int warp_m = wid & 3, warp_n = wid >> 2;
    const int rbase = blockIdx.x * 128;

    // ---------------- Phase 1: aggregation into smem A tile ----------------
    {
        const uint2* h1v = (const uint2*)g_h1;   // 32 uint2 per row (128 halves)
        float4 bb = ((const float4*)b1)[lane];   // channels lane*4..lane*4+3

        for (int rr = wid; rr < 128; rr += 8) {
            int gw = rbase + rr;
            uint2 ov = make_uint2(0u, 0u);
            if (gw < NN) {
                int start = g_rowstart[gw];
                int cnt   = g_deg[gw] - 1;
                float dd  = g_dinv[gw];
                float4 acc = make_float4(0.f, 0.f, 0.f, 0.f);

                int i = 0;
                for (; i + 1 < cnt; i += 2) {
                    int s0 = g_csr[start + i];
                    int s1 = g_csr[start + i + 1];
                    float c0 = dd * g_dinv[s0];
                    float c1 = dd * g_dinv[s1];
                    uint2 r0 = h1v[(size_t)s0 * 32 + lane];
                    uint2 r1 = h1v[(size_t)s1 * 32 + lane];
                    float2 a0 = __half22float2(*(__half2*)&r0.x);
                    float2 a1 = __half22float2(*(__half2*)&r0.y);
                    float2 b0 = __half22float2(*(__half2*)&r1.x);
                    float2 b1_ = __half22float2(*(__half2*)&r1.y);
                    acc.x += c0 * a0.x + c1 * b0.x;
                    acc.y += c0 * a0.y + c1 * b0.y;
                    acc.z += c0 * a1.x + c1 * b1_.x;
                    acc.w += c0 * a1.y + c1 * b1_.y;
                }
                if (i < cnt) {
                    int s0 = g_csr[start + i];
                    float c0 = dd * g_dinv[s0];
                    uint2 r0 = h1v[(size_t)s0 * 32 + lane];
                    float2 a0 = __half22float2(*(__half2*)&r0.x);
                    float2 a1 = __half22float2(*(__half2*)&r0.y);
                    acc.x += c0 * a0.x; acc.y += c0 * a0.y;
                    acc.z += c0 * a1.x; acc.w += c0 * a1.y;
                }

                float c2 = dd * dd;
                uint2 rs = h1v[(size_t)gw * 32 + lane];
                float2 s0f = __half22float2(*(__half2*)&rs.x);
                float2 s1f = __half22float2(*(__half2*)&rs.y);
                float ox = fmaxf(acc.x + c2 * s0f.x + bb.x, 0.f);
                float oy = fmaxf(acc.y + c2 * s0f.y + bb.y, 0.f);
                float oz = fmaxf(acc.z + c2 * s1f.x + bb.z, 0.f);
                float ow = fmaxf(acc.w + c2 * s1f.y + bb.w, 0.f);
                *(__half2*)&ov.x = __floats2half2_rn(ox, oy);
                *(__half2*)&ov.y = __floats2half2_rn(oz, ow);
            }
            *(uint2*)&Ax[rr * AST + lane * 4] = ov;
        }
    }
    __syncthreads();

    // ---------------- Phase 2: GEMM2 on the smem tile ----------------
    const uint32_t ax_b = s2u(Ax);
    const uint32_t bh_b = s2u(Bh), bl_b = s2u(Bl);

    float acc[2][NT8][4];
    #pragma unroll
    for (int a = 0; a < 2; a++)
        #pragma unroll
        for (int b = 0; b < NT8; b++)
            #pragma unroll
            for (int c = 0; c < 4; c++) acc[a][b][c] = 0.f;

    const int a_row = (lane & 15);
    const int a_col = 8 * (lane >> 4);
    const int b_row = (lane & 15);
    const int b_col = 8 * (lane >> 4);

    for (int ch = 0; ch < KT / KC; ch++) {
        const int c0 = ch * KC;

        // stage B chunk: 32 x 64 fp16 hi/lo
        #pragma unroll
        for (int i = 0; i < (KC * NC4) / 256; i++) {
            int idx = tid + i * 256;
            int k = idx / NC4, n4 = idx % NC4;
            int e = k * BST + n4 * 4;
            size_t ge = (size_t)(c0 + k) * NC + n4 * 4;
            *(uint2*)&Bh[e] = *(const uint2*)&g_w2h[ge];
            *(uint2*)&Bl[e] = *(const uint2*)&g_w2l[ge];
        }
        __syncthreads();

        #pragma unroll
        for (int ks = 0; ks < 2; ks++) {
            const int k16 = c0 + ks * 16;
            uint32_t af[2][4];
            #pragma unroll
            for (int mi = 0; mi < 2; mi++) {
                uint32_t off = (uint32_t)(((warp_m * 32 + mi * 16 + a_row) * AST
                                           + k16 + a_col) * 2);
                ldsm4(af[mi], ax_b + off);
            }
            #pragma unroll
            for (int ni = 0; ni < NT16; ni++) {
                uint32_t off = (uint32_t)((((ks * 16) + b_row) * BST
                                           + warp_n * NWN + ni * 16 + b_col) * 2);
                uint32_t bfh[4], bfl[4];
                ldsm4t(bfh, bh_b + off);
                ldsm4t(bfl, bl_b + off);
                #pragma unroll
                for (int mi = 0; mi < 2; mi++) {
                    mma16816h(acc[mi][2 * ni],     af[mi], bfh[0], bfh[1]);
                    mma16816h(acc[mi][2 * ni + 1], af[mi], bfh[2], bfh[3]);
                    mma16816h(acc[mi][2 * ni],     af[mi], bfl[0], bfl[1]);
                    mma16816h(acc[mi][2 * ni + 1], af[mi], bfl[2], bfl[3]);
                }
            }
        }
        __syncthreads();
    }

    // epilogue: pre-scale by dinv[row], write fp16 h2
    const int g = lane >> 2, tig = lane & 3;
    #pragma unroll
    for (int mi = 0; mi < 2; mi++) {
        int row0 = rbase + warp_m * 32 + mi * 16 + g;
        float dv0 = (row0 < NN) ? g_dinv[row0] : 0.f;
        float dv8 = (row0 + 8 < NN) ? g_dinv[row0 + 8] : 0.f;
        #pragma unroll
        for (int ni = 0; ni < NT8; ni++) {
            int col = warp_n * NWN + ni * 8 + tig * 2;
            if (row0 < NN)
                *(__half2*)&g_h2[(size_t)row0 * NC + col] =
                    __floats2half2_rn(acc[mi][ni][0] * dv0, acc[mi][ni][1] * dv0);
            if (row0 + 8 < NN)
                *(__half2*)&g_h2[(size_t)(row0 + 8) * NC + col] =
                    __floats2half2_rn(acc[mi][ni][2] * dv8, acc[mi][ni][3] * dv8);
        }
    }
}

// ---------------- Layer-2 aggregation (h2 pre-scaled by dinv) + bias + log_softmax ----
__global__ void k_agg2(const float* __restrict__ b2, float* __restrict__ out) {
    int gw   = (blockIdx.x * blockDim.x + threadIdx.x) >> 5;
    int lane = threadIdx.x & 31;
    if (gw >= NN) return;

    int start = g_rowstart[gw];
    int cnt   = g_deg[gw] - 1;
    float dd  = g_dinv[gw];

    const __half2* h2v = (const __half2*)g_h2;   // 32 half2 per row
    float2 acc = make_float2(0.f, 0.f);

    int i = 0;
    for (; i + 1 < cnt; i += 2) {
        int s0 = g_csr[start + i];
        int s1 = g_csr[start + i + 1];
        float2 v0 = __half22float2(h2v[(size_t)s0 * 32 + lane]);
        float2 v1 = __half22float2(h2v[(size_t)s1 * 32 + lane]);
        acc.x += v0.x + v1.x;
        acc.y += v0.y + v1.y;
    }
    if (i < cnt) {
        int s0 = g_csr[start + i];
        float2 v0 = __half22float2(h2v[(size_t)s0 * 32 + lane]);
        acc.x += v0.x;
        acc.y += v0.y;
    }

    float2 hv = __half22float2(h2v[(size_t)gw * 32 + lane]);
    float2 bb = ((const float2*)b2)[lane];
    float a = dd * (acc.x + hv.x) + bb.x;
    float b = dd * (acc.y + hv.y) + bb.y;

    float m = fmaxf(a, b);
    #pragma unroll
    for (int off = 16; off > 0; off >>= 1)
        m = fmaxf(m, __shfl_xor_sync(0xFFFFFFFFu, m, off));
    float s = expf(a - m) + expf(b - m);
    #pragma unroll
    for (int off = 16; off > 0; off >>= 1)
        s += __shfl_xor_sync(0xFFFFFFFFu, s, off);
    float l = m + logf(s);

    float2 o = make_float2(a - l, b - l);
    ((float2*)out)[(size_t)gw * 32 + lane] = o;
}

// ---------------- launch ----------------
extern "C" void kernel_launch(void* const* d_in, const int* in_sizes, int n_in,
                              void* d_out, int out_size) {
    const float* x   = (const float*)d_in[0];
    const void*  ei  = (const void*)d_in[1];
    const float* W1  = (const float*)d_in[2];
    const float* b1  = (const float*)d_in[3];
    const float* W2  = (const float*)d_in[4];
    const float* b2  = (const float*)d_in[5];
    float*       out = (float*)d_out;

    static cudaStream_t s_side = nullptr, s_dv = nullptr;
    static cudaEvent_t  ev_fork = nullptr, ev_join = nullptr,
                        ev_cvt = nullptr, ev_dv = nullptr;
    if (s_side == nullptr) {
        cudaStreamCreateWithFlags(&s_side, cudaStreamNonBlocking);
        cudaStreamCreateWithFlags(&s_dv, cudaStreamNonBlocking);
        cudaEventCreateWithFlags(&ev_fork, cudaEventDisableTiming);
        cudaEventCreateWithFlags(&ev_join, cudaEventDisableTiming);
        cudaEventCreateWithFlags(&ev_cvt, cudaEventDisableTiming);
        cudaEventCreateWithFlags(&ev_dv, cudaEventDisableTiming);
    }

    // ---- fork: CSR chain on side stream ----
    cudaEventRecord(ev_fork, 0);
    cudaStreamWaitEvent(s_side, ev_fork, 0);
    k_deg_init_detect<<<(NN + 255) / 256, 256, 0, s_side>>>(ei);
    k_convert<<<(NE + 255) / 256, 256, 0, s_side>>>(ei);
    cudaEventRecord(ev_cvt, s_side);

    // dinv runs parallel with the scan chain
    cudaStreamWaitEvent(s_dv, ev_cvt, 0);
    k_dinv<<<(NN + 255) / 256, 256, 0, s_dv>>>();
    cudaEventRecord(ev_dv, s_dv);

    k_scan_partial<<<NBLK_SCAN, 1024, 0, s_side>>>();
    k_scan_base<<<1, 128, 0, s_side>>>();
    k_scan_write<<<NBLK_SCAN, 1024, 0, s_side>>>();
    k_fill<<<(NE + 255) / 256, 256, 0, s_side>>>(ei);
    cudaEventRecord(ev_join, s_side);

    // ---- main stream: weight split + layer-1 GEMM (independent of CSR) ----
    k_wsplit<<<(F0 * F1 + F1 * F2 + 255) / 256, 256>>>(W1, W2);
    k_mma1<<<NTILE, 256>>>(x);

    // ---- join, then the fused tail ----
    cudaStreamWaitEvent(0, ev_join, 0);
    cudaStreamWaitEvent(0, ev_dv, 0);
    k_agg1_mma2<<<NTILE, 256>>>(b1);
    k_agg2<<<(NN * 32 + 255) / 256, 256>>>(b2, out);
}

// round 14
// speedup vs baseline: 1.1481x; 1.1481x over previous
#include <cuda_runtime.h>
#include <cuda_fp16.h>
#include <cstdint>

#define NN 100000
#define NE 1600000
#define F0 256
#define F1 128
#define F2 64
#define NBLK_SCAN 98   // ceil(NN/1024)
#define NTILE 782      // ceil(NN/128)

// ---- scratch (device globals; no allocation allowed) ----
__device__ __align__(16) __half g_h1[NN * F1];   // x @ W1            (fp16 gather operand)
__device__ __align__(16) __half g_hr[NN * F1];   // relu(agg1+b1)     (fp16: GEMM2 A input)
__device__ __align__(16) __half g_h2[NN * F2];   // dinv*(hr @ W2)    (fp16, pre-scaled)
__device__ float g_dinv[NN];
__device__ int   g_deg[NN];
__device__ int   g_rowstart[NN];
__device__ int   g_cursor[NN];
__device__ int   g_csr[NE];
__device__ int   g_dst[NE];
__device__ int   g_is32;
__device__ int   g_sagg[128];    // scan: per-block aggregates
__device__ int   g_sflag[128];   // scan: publish flags (cleared each replay)

// ================= mma.sync helpers (sm_80+ PTX; safe on base sm_103) =========
__device__ __forceinline__ uint32_t s2u(const void* p) {
    uint32_t a;
    asm("{ .reg .u64 t; cvta.to.shared.u64 t, %1; cvt.u32.u64 %0, t; }" : "=r"(a) : "l"(p));
    return a;
}

__device__ __forceinline__ void ldsm4(uint32_t* r, uint32_t a) {
    asm volatile("ldmatrix.sync.aligned.m8n8.x4.shared.b16 {%0,%1,%2,%3}, [%4];"
                 : "=r"(r[0]), "=r"(r[1]), "=r"(r[2]), "=r"(r[3]) : "r"(a));
}
__device__ __forceinline__ void ldsm4t(uint32_t* r, uint32_t a) {
    asm volatile("ldmatrix.sync.aligned.m8n8.x4.trans.shared.b16 {%0,%1,%2,%3}, [%4];"
                 : "=r"(r[0]), "=r"(r[1]), "=r"(r[2]), "=r"(r[3]) : "r"(a));
}
__device__ __forceinline__ void mma16816h(float* c, const uint32_t* a,
                                          uint32_t b0, uint32_t b1) {
    asm volatile("mma.sync.aligned.m16n8k16.row.col.f32.f16.f16.f32 "
                 "{%0,%1,%2,%3}, {%4,%5,%6,%7}, {%8,%9}, {%0,%1,%2,%3};"
                 : "+f"(c[0]), "+f"(c[1]), "+f"(c[2]), "+f"(c[3])
                 : "r"(a[0]), "r"(a[1]), "r"(a[2]), "r"(a[3]), "r"(b0), "r"(b1));
}

// split fp32 -> (hi, lo) fp16 pair
__device__ __forceinline__ void split16(float v, __half& h, __half& l) {
    h = __float2half_rn(v);
    l = __float2half_rn(v - __half2float(h));
}

// -------- combined degree init + edge dtype detect + scan-flag clear --------
__global__ void k_deg_init_detect(const void* __restrict__ ei) {
    int i = blockIdx.x * blockDim.x + threadIdx.x;
    if (i < NN) g_deg[i] = 1;   // +1 self loop baked in
    if (i < 128) g_sflag[i] = 0;
    if (i == 0) {
        const long long* e64 = (const long long*)ei;
        int ok64 = 1;
        for (int j = 0; j < 128; j++) {
            long long v = e64[j];
            if (v < 0 || v >= NN) { ok64 = 0; break; }
        }
        g_is32 = ok64 ? 0 : 1;
    }
}

__global__ void k_convert(const void* __restrict__ ei) {
    int i = blockIdx.x * blockDim.x + threadIdx.x;
    if (i >= NE) return;
    int v;
    if (g_is32) v = ((const int*)ei)[NE + i];
    else        v = (int)((const long long*)ei)[NE + i];
    g_dst[i] = v;
    if (v >= 0 && v < NN) atomicAdd(&g_deg[v], 1);   // fused degree count
}

// ---------------- single-kernel scan (decoupled lookback) + dinv ----------------
// 98 blocks, all co-resident (148 SMs) -> predecessor spin is safe.
__global__ void __launch_bounds__(1024) k_scan_fused() {
    int t = threadIdx.x, lane = t & 31, w = t >> 5, b = blockIdx.x;
    int i = b * 1024 + t;
    int deg = (i < NN) ? g_deg[i] : 1;
    int v = deg - 1;

    // block inclusive scan: warp shfl scan + warp-total scan
    int x = v;
    #pragma unroll
    for (int o = 1; o < 32; o <<= 1) {
        int u = __shfl_up_sync(0xFFFFFFFFu, x, o);
        if (lane >= o) x += u;
    }
    __shared__ int ws[32];
    if (lane == 31) ws[w] = x;
    __syncthreads();
    if (t < 32) {
        int s = ws[t];
        #pragma unroll
        for (int o = 1; o < 32; o <<= 1) {
            int u = __shfl_up_sync(0xFFFFFFFFu, s, o);
            if (lane >= o) s += u;
        }
        ws[t] = s;
    }
    __syncthreads();
    int xin = x + (w > 0 ? ws[w - 1] : 0);   // inclusive prefix within block
    int blocktot = ws[31];

    // publish this block's aggregate
    if (t == 0) {
        g_sagg[b] = blocktot;
        __threadfence();
        *(volatile int*)&g_sflag[b] = 1;
    }

    // exclusive base = sum of predecessor aggregates (parallel poll, exact int add)
    __shared__ int base_sh;
    if (t == 0) base_sh = 0;
    __syncthreads();
    if (t < b) {
        while (*(volatile int*)&g_sflag[t] == 0) {}
        atomicAdd(&base_sh, *(volatile int*)&g_sagg[t]);
    }
    __syncthreads();

    if (i < NN) {
        int start = base_sh + xin - v;   // exclusive prefix
        g_rowstart[i] = start;
        g_cursor[i]   = start;
        g_dinv[i]     = rsqrtf((float)deg);
    }
}

__global__ void k_fill(const void* __restrict__ ei) {
    int i = blockIdx.x * blockDim.x + threadIdx.x;
    if (i < NE) {
        int d = g_dst[i];
        if (d < 0 || d >= NN) return;
        int s;
        if (g_is32) s = ((const int*)ei)[i];
        else        s = (int)((const long long*)ei)[i];
        int pos = atomicAdd(&g_cursor[d], 1);
        if (pos >= 0 && pos < NE) g_csr[pos] = s;
    }
}

// =======================================================================
// GEMM1 (fp16 A exact, W1 split to fp16 hi/lo in-register, 2-pass):
//   g_h1[M,128](fp16) = x[M,256](fp32->fp16) @ W1(fp32)
// CTA: 128 rows x 128 cols, 256 threads = 8 warps (4 M x 2 N). K chunk 32.
// =======================================================================
__global__ void __launch_bounds__(256, 2) k_mma1(const float* __restrict__ Ain,
                                                const float* __restrict__ Wg) {
    constexpr int NC = F1, KT = F0;
    constexpr int KC   = 32;
    constexpr int AST  = 40;
    constexpr int BST  = NC + 8;
    constexpr int NWN  = NC / 2;
    constexpr int NT8  = NWN / 8;
    constexpr int NT16 = NWN / 16;
    constexpr int NC4  = NC / 4;

    __shared__ __align__(16) __half Ax[128 * AST];
    __shared__ __align__(16) __half Bh[KC * BST];
    __shared__ __align__(16) __half Bl[KC * BST];

    const int tid = threadIdx.x, lane = tid & 31, wid = tid >> 5;
    const int warp_m = wid & 3, warp_n = wid >> 2;
    const int rbase = blockIdx.x * 128;

    const uint32_t ax_b = s2u(Ax);
    const uint32_t bh_b = s2u(Bh), bl_b = s2u(Bl);

    float acc[2][NT8][4];
    #pragma unroll
    for (int a = 0; a < 2; a++)
        #pragma unroll
        for (int b = 0; b < NT8; b++)
            #pragma unroll
            for (int c = 0; c < 4; c++) acc[a][b][c] = 0.f;

    const int a_row = (lane & 15);
    const int a_col = 8 * (lane >> 4);
    const int b_row = (lane & 15);
    const int b_col = 8 * (lane >> 4);

    const float4* av = (const float4*)Ain;
    constexpr int ROWF4 = KT / 4;

    for (int ch = 0; ch < KT / KC; ch++) {
        const int c0 = ch * KC;

        // ---- stage A chunk: 128 x 32 fp32 -> fp16 (exact within fp16) ----
        #pragma unroll
        for (int i = 0; i < 4; i++) {
            int idx = tid + i * 256;
            int r = idx >> 3;
            int f = idx & 7;
            float4 v = make_float4(0.f, 0.f, 0.f, 0.f);
            int gr = rbase + r;
            if (gr < NN) v = av[(size_t)gr * ROWF4 + (c0 >> 2) + f];
            uint2 p;
            *(__half2*)&p.x = __floats2half2_rn(v.x, v.y);
            *(__half2*)&p.y = __floats2half2_rn(v.z, v.w);
            *(uint2*)&Ax[r * AST + f * 4] = p;
        }

        // ---- stage B chunk from fp32 W: 32 x 128, split hi/lo in-register ----
        #pragma unroll
        for (int i = 0; i < (KC * NC4) / 256; i++) {
            int idx = tid + i * 256;
            int k = idx / NC4, n4 = idx % NC4;
            float4 wv = *(const float4*)&Wg[(size_t)(c0 + k) * NC + n4 * 4];
            __half hx, lx, hy, ly, hz, lz, hw, lw;
            split16(wv.x, hx, lx); split16(wv.y, hy, ly);
            split16(wv.z, hz, lz); split16(wv.w, hw, lw);
            int e = k * BST + n4 * 4;
            uint2 ph, pl;
            *(__half2*)&ph.x = __halves2half2(hx, hy);
            *(__half2*)&ph.y = __halves2half2(hz, hw);
            *(__half2*)&pl.x = __halves2half2(lx, ly);
            *(__half2*)&pl.y = __halves2half2(lz, lw);
            *(uint2*)&Bh[e] = ph;
            *(uint2*)&Bl[e] = pl;
        }
        __syncthreads();

        #pragma unroll
        for (int ks = 0; ks < 2; ks++) {
            const int k16 = ks * 16;
            uint32_t af[2][4];
            #pragma unroll
            for (int mi = 0; mi < 2; mi++) {
                uint32_t off = (uint32_t)(((warp_m * 32 + mi * 16 + a_row) * AST
                                           + k16 + a_col) * 2);
                ldsm4(af[mi], ax_b + off);
            }
            #pragma unroll
            for (int ni = 0; ni < NT16; ni++) {
                uint32_t off = (uint32_t)(((k16 + b_row) * BST
                                           + warp_n * NWN + ni * 16 + b_col) * 2);
                uint32_t bfh[4], bfl[4];
                ldsm4t(bfh, bh_b + off);
                ldsm4t(bfl, bl_b + off);
                #pragma unroll
                for (int mi = 0; mi < 2; mi++) {
                    mma16816h(acc[mi][2 * ni],     af[mi], bfh[0], bfh[1]);
                    mma16816h(acc[mi][2 * ni + 1], af[mi], bfh[2], bfh[3]);
                    mma16816h(acc[mi][2 * ni],     af[mi], bfl[0], bfl[1]);
                    mma16816h(acc[mi][2 * ni + 1], af[mi], bfl[2], bfl[3]);
                }
            }
        }
        __syncthreads();
    }

    const int g = lane >> 2, tig = lane & 3;
    #pragma unroll
    for (int mi = 0; mi < 2; mi++) {
        int row0 = rbase + warp_m * 32 + mi * 16 + g;
        #pragma unroll
        for (int ni = 0; ni < NT8; ni++) {
            int col = warp_n * NWN + ni * 8 + tig * 2;
            if (row0 < NN)
                *(__half2*)&g_h1[(size_t)row0 * NC + col] =
                    __floats2half2_rn(acc[mi][ni][0], acc[mi][ni][1]);
            if (row0 + 8 < NN)
                *(__half2*)&g_h1[(size_t)(row0 + 8) * NC + col] =
                    __floats2half2_rn(acc[mi][ni][2], acc[mi][ni][3]);
        }
    }
}

// =======================================================================
// GEMM2 (fp16 A exact, W2 split in-register, 2-pass) + dinv pre-scale:
//   g_h2[M,64](fp16) = dinv[row] * (g_hr[M,128](fp16) @ W2(fp32))
// =======================================================================
__global__ void __launch_bounds__(256, 2) k_mma2(const float* __restrict__ Wg) {
    constexpr int NC = F2, KT = F1;
    constexpr int KC   = 32;
    constexpr int AST  = 40;
    constexpr int BST  = NC + 8;
    constexpr int NWN  = NC / 2;
    constexpr int NT8  = NWN / 8;
    constexpr int NT16 = NWN / 16;
    constexpr int NC4  = NC / 4;

    __shared__ __align__(16) __half Ax[128 * AST];
    __shared__ __align__(16) __half Bh[KC * BST];
    __shared__ __align__(16) __half Bl[KC * BST];

    const int tid = threadIdx.x, lane = tid & 31, wid = tid >> 5;
    const int warp_m = wid & 3, warp_n = wid >> 2;
    const int rbase = blockIdx.x * 128;

    const uint32_t ax_b = s2u(Ax);
    const uint32_t bh_b = s2u(Bh), bl_b = s2u(Bl);

    float acc[2][NT8][4];
    #pragma unroll
    for (int a = 0; a < 2; a++)
        #pragma unroll
        for (int b = 0; b < NT8; b++)
            #pragma unroll
            for (int c = 0; c < 4; c++) acc[a][b][c] = 0.f;

    const int a_row = (lane & 15);
    const int a_col = 8 * (lane >> 4);
    const int b_row = (lane & 15);
    const int b_col = 8 * (lane >> 4);

    for (int ch = 0; ch < KT / KC; ch++) {
        const int c0 = ch * KC;

        #pragma unroll
        for (int i = 0; i < 4; i++) {
            int idx = tid + i * 256;
            int r = idx >> 3;
            int q = idx & 7;
            uint2 v = make_uint2(0u, 0u);
            int gr = rbase + r;
            if (gr < NN) v = *(const uint2*)&g_hr[(size_t)gr * KT + c0 + q * 4];
            *(uint2*)&Ax[r * AST + q * 4] = v;
        }

        #pragma unroll
        for (int i = 0; i < (KC * NC4) / 256; i++) {
            int idx = tid + i * 256;
            int k = idx / NC4, n4 = idx % NC4;
            float4 wv = *(const float4*)&Wg[(size_t)(c0 + k) * NC + n4 * 4];
            __half hx, lx, hy, ly, hz, lz, hw, lw;
            split16(wv.x, hx, lx); split16(wv.y, hy, ly);
            split16(wv.z, hz, lz); split16(wv.w, hw, lw);
            int e = k * BST + n4 * 4;
            uint2 ph, pl;
            *(__half2*)&ph.x = __halves2half2(hx, hy);
            *(__half2*)&ph.y = __halves2half2(hz, hw);
            *(__half2*)&pl.x = __halves2half2(lx, ly);
            *(__half2*)&pl.y = __halves2half2(lz, lw);
            *(uint2*)&Bh[e] = ph;
            *(uint2*)&Bl[e] = pl;
        }
        __syncthreads();

        #pragma unroll
        for (int ks = 0; ks < 2; ks++) {
            const int k16 = ks * 16;
            uint32_t af[2][4];
            #pragma unroll
            for (int mi = 0; mi < 2; mi++) {
                uint32_t off = (uint32_t)(((warp_m * 32 + mi * 16 + a_row) * AST
                                           + k16 + a_col) * 2);
                ldsm4(af[mi], ax_b + off);
            }
            #pragma unroll
            for (int ni = 0; ni < NT16; ni++) {
                uint32_t off = (uint32_t)(((k16 + b_row) * BST
                                           + warp_n * NWN + ni * 16 + b_col) * 2);
                uint32_t bfh[4], bfl[4];
                ldsm4t(bfh, bh_b + off);
                ldsm4t(bfl, bl_b + off);
                #pragma unroll
                for (int mi = 0; mi < 2; mi++) {
                    mma16816h(acc[mi][2 * ni],     af[mi], bfh[0], bfh[1]);
                    mma16816h(acc[mi][2 * ni + 1], af[mi], bfh[2], bfh[3]);
                    mma16816h(acc[mi][2 * ni],     af[mi], bfl[0], bfl[1]);
                    mma16816h(acc[mi][2 * ni + 1], af[mi], bfl[2], bfl[3]);
                }
            }
        }
        __syncthreads();
    }

    // ---- epilogue: pre-scale by dinv[row], write fp16 ----
    const int g = lane >> 2, tig = lane & 3;
    #pragma unroll
    for (int mi = 0; mi < 2; mi++) {
        int row0 = rbase + warp_m * 32 + mi * 16 + g;
        float dv0 = (row0 < NN) ? g_dinv[row0] : 0.f;
        float dv8 = (row0 + 8 < NN) ? g_dinv[row0 + 8] : 0.f;
        #pragma unroll
        for (int ni = 0; ni < NT8; ni++) {
            int col = warp_n * NWN + ni * 8 + tig * 2;
            if (row0 < NN)
                *(__half2*)&g_h2[(size_t)row0 * NC + col] =
                    __floats2half2_rn(acc[mi][ni][0] * dv0, acc[mi][ni][1] * dv0);
            if (row0 + 8 < NN)
                *(__half2*)&g_h2[(size_t)(row0 + 8) * NC + col] =
                    __floats2half2_rn(acc[mi][ni][2] * dv8, acc[mi][ni][3] * dv8);
        }
    }
}

// ---------------- Layer-1 aggregation (fp16 gather) + bias + ReLU -> fp16 ----------------
__global__ void k_agg1(const float* __restrict__ b1) {
    int gw   = (blockIdx.x * blockDim.x + threadIdx.x) >> 5;
    int lane = threadIdx.x & 31;
    if (gw >= NN) return;

    int start = g_rowstart[gw];
    int cnt   = g_deg[gw] - 1;
    float dd  = g_dinv[gw];

    const uint2* h1v = (const uint2*)g_h1;   // 32 uint2 per row (128 halves)
    float4 acc = make_float4(0.f, 0.f, 0.f, 0.f);

    int i = 0;
    for (; i + 1 < cnt; i += 2) {
        int s0 = g_csr[start + i];
        int s1 = g_csr[start + i + 1];
        float c0 = dd * g_dinv[s0];
        float c1 = dd * g_dinv[s1];
        uint2 r0 = h1v[(size_t)s0 * 32 + lane];
        uint2 r1 = h1v[(size_t)s1 * 32 + lane];
        float2 a0 = __half22float2(*(__half2*)&r0.x);
        float2 a1 = __half22float2(*(__half2*)&r0.y);
        float2 b0 = __half22float2(*(__half2*)&r1.x);
        float2 b1_ = __half22float2(*(__half2*)&r1.y);
        acc.x += c0 * a0.x + c1 * b0.x;
        acc.y += c0 * a0.y + c1 * b0.y;
        acc.z += c0 * a1.x + c1 * b1_.x;
        acc.w += c0 * a1.y + c1 * b1_.y;
    }
    if (i < cnt) {
        int s0 = g_csr[start + i];
        float c0 = dd * g_dinv[s0];
        uint2 r0 = h1v[(size_t)s0 * 32 + lane];
        float2 a0 = __half22float2(*(__half2*)&r0.x);
        float2 a1 = __half22float2(*(__half2*)&r0.y);
        acc.x += c0 * a0.x; acc.y += c0 * a0.y;
        acc.z += c0 * a1.x; acc.w += c0 * a1.y;
    }

    float c2 = dd * dd;
    uint2 rs = h1v[(size_t)gw * 32 + lane];
    float2 s0f = __half22float2(*(__half2*)&rs.x);
    float2 s1f = __half22float2(*(__half2*)&rs.y);
    float4 bb = ((const float4*)b1)[lane];
    float ox = fmaxf(acc.x + c2 * s0f.x + bb.x, 0.f);
    float oy = fmaxf(acc.y + c2 * s0f.y + bb.y, 0.f);
    float oz = fmaxf(acc.z + c2 * s1f.x + bb.z, 0.f);
    float ow = fmaxf(acc.w + c2 * s1f.y + bb.w, 0.f);

    uint2 ov;
    *(__half2*)&ov.x = __floats2half2_rn(ox, oy);
    *(__half2*)&ov.y = __floats2half2_rn(oz, ow);
    ((uint2*)g_hr)[(size_t)gw * 32 + lane] = ov;
}

// ---------------- Layer-2 aggregation (h2 pre-scaled by dinv) + bias + log_softmax ----
__global__ void k_agg2(const float* __restrict__ b2, float* __restrict__ out) {
    int gw   = (blockIdx.x * blockDim.x + threadIdx.x) >> 5;
    int lane = threadIdx.x & 31;
    if (gw >= NN) return;

    int start = g_rowstart[gw];
    int cnt   = g_deg[gw] - 1;
    float dd  = g_dinv[gw];

    const __half2* h2v = (const __half2*)g_h2;   // 32 half2 per row
    float2 acc = make_float2(0.f, 0.f);

    int i = 0;
    for (; i + 1 < cnt; i += 2) {
        int s0 = g_csr[start + i];
        int s1 = g_csr[start + i + 1];
        float2 v0 = __half22float2(h2v[(size_t)s0 * 32 + lane]);
        float2 v1 = __half22float2(h2v[(size_t)s1 * 32 + lane]);
        acc.x += v0.x + v1.x;
        acc.y += v0.y + v1.y;
    }
    if (i < cnt) {
        int s0 = g_csr[start + i];
        float2 v0 = __half22float2(h2v[(size_t)s0 * 32 + lane]);
        acc.x += v0.x;
        acc.y += v0.y;
    }

    float2 hv = __half22float2(h2v[(size_t)gw * 32 + lane]);
    float2 bb = ((const float2*)b2)[lane];
    float a = dd * (acc.x + hv.x) + bb.x;
    float b = dd * (acc.y + hv.y) + bb.y;

    float m = fmaxf(a, b);
    #pragma unroll
    for (int off = 16; off > 0; off >>= 1)
        m = fmaxf(m, __shfl_xor_sync(0xFFFFFFFFu, m, off));
    float s = expf(a - m) + expf(b - m);
    #pragma unroll
    for (int off = 16; off > 0; off >>= 1)
        s += __shfl_xor_sync(0xFFFFFFFFu, s, off);
    float l = m + logf(s);

    float2 o = make_float2(a - l, b - l);
    ((float2*)out)[(size_t)gw * 32 + lane] = o;
}

// ---------------- launch ----------------
// Fork/join inside graph capture:
//   side stream : deg_init+detect+flagclear -> convert -> scan_fused(+dinv) -> fill
//   main stream : mma1 (reads W1 fp32 directly)
// join before agg1 -> mma2 -> agg2.
extern "C" void kernel_launch(void* const* d_in, const int* in_sizes, int n_in,
                              void* d_out, int out_size) {
    const float* x   = (const float*)d_in[0];
    const void*  ei  = (const void*)d_in[1];
    const float* W1  = (const float*)d_in[2];
    const float* b1  = (const float*)d_in[3];
    const float* W2  = (const float*)d_in[4];
    const float* b2  = (const float*)d_in[5];
    float*       out = (float*)d_out;

    static cudaStream_t s_side = nullptr;
    static cudaEvent_t  ev_fork = nullptr, ev_join = nullptr;
    if (s_side == nullptr) {
        cudaStreamCreateWithFlags(&s_side, cudaStreamNonBlocking);
        cudaEventCreateWithFlags(&ev_fork, cudaEventDisableTiming);
        cudaEventCreateWithFlags(&ev_join, cudaEventDisableTiming);
    }

    // ---- fork: CSR chain on side stream ----
    cudaEventRecord(ev_fork, 0);
    cudaStreamWaitEvent(s_side, ev_fork, 0);
    k_deg_init_detect<<<(NN + 255) / 256, 256, 0, s_side>>>(ei);
    k_convert<<<(NE + 255) / 256, 256, 0, s_side>>>(ei);
    k_scan_fused<<<NBLK_SCAN, 1024, 0, s_side>>>();
    k_fill<<<(NE + 255) / 256, 256, 0, s_side>>>(ei);
    cudaEventRecord(ev_join, s_side);

    // ---- main stream: layer-1 GEMM (independent of CSR) ----
    k_mma1<<<NTILE, 256>>>(x, W1);

    // ---- join, then the dependent tail ----
    cudaStreamWaitEvent(0, ev_join, 0);
    k_agg1<<<(NN * 32 + 255) / 256, 256>>>(b1);
    k_mma2<<<NTILE, 256>>>(W2);
    k_agg2<<<(NN * 32 + 255) / 256, 256>>>(b2, out);
}